// round 14
// baseline (speedup 1.0000x reference)
#include <cuda_runtime.h>
#include <cstdint>
#include <math.h>

// Problem constants
#define BB 8
#define SS 2048
#define DD 1024
#define MTOT (BB * SS)   // 16384

typedef int8_t s8;

// ---------------------------------------------------------------------------
// Scratch (device globals; no allocation allowed)
// ---------------------------------------------------------------------------
__device__ float g_s[(size_t)BB * SS * SS];                    // fp32 scores
__device__ s8 g_in1[3 * (size_t)MTOT * DD], g_in2[3 * (size_t)MTOT * DD];
__device__ s8 g_w1[4 * (size_t)DD * DD],  g_w2[4 * (size_t)DD * DD];
__device__ float g_qkvf[3 * (size_t)MTOT * DD];                // q,k,v fp32
__device__ s8 g_qk1[2 * (size_t)MTOT * DD], g_qk2[2 * (size_t)MTOT * DD];
__device__ s8 g_vt1[(size_t)BB * DD * SS], g_vt2[(size_t)BB * DD * SS];
__device__ s8 g_p1[(size_t)BB * SS * SS], g_p2[(size_t)BB * SS * SS];
__device__ float g_xf[(size_t)MTOT * DD];
__device__ s8 g_x1[(size_t)MTOT * DD], g_x2[(size_t)MTOT * DD];
__device__ float g_sin[3 * MTOT], g_sw[4 * DD], g_sqk[2 * MTOT];
__device__ float g_sv[BB * DD], g_sp[BB * SS], g_sx[MTOT];
__device__ float g_bias3[3 * DD];

// ---------------------------------------------------------------------------
// PTX helpers
// ---------------------------------------------------------------------------
__device__ __forceinline__ uint32_t smem_u32(const void* p) {
    uint32_t a;
    asm("{ .reg .u64 t; cvta.to.shared.u64 t, %1; cvt.u32.u64 %0, t; }"
        : "=r"(a) : "l"(p));
    return a;
}

#define CPA16(dst, src) \
    asm volatile("cp.async.cg.shared.global [%0], [%1], 16;" :: "r"(dst), "l"(src))
#define CP_COMMIT() asm volatile("cp.async.commit_group;" ::: "memory")
#define CP_WAIT0()  asm volatile("cp.async.wait_group 0;" ::: "memory")

#define LDSM4(r0, r1, r2, r3, addr) \
    asm volatile("ldmatrix.sync.aligned.m8n8.x4.shared.b16 {%0,%1,%2,%3}, [%4];" \
                 : "=r"(r0), "=r"(r1), "=r"(r2), "=r"(r3) : "r"(addr))

// int8 IMMA m16n8k32, s32 accumulate (exact integer arithmetic)
#define MMA_S8(d, a, b0, b1)                                                 \
    asm volatile(                                                            \
        "mma.sync.aligned.m16n8k32.row.col.s32.s8.s8.s32 "                   \
        "{%0,%1,%2,%3}, {%4,%5,%6,%7}, {%8,%9}, {%0,%1,%2,%3};"              \
        : "+r"((d)[0]), "+r"((d)[1]), "+r"((d)[2]), "+r"((d)[3])             \
        : "r"((a)[0]), "r"((a)[1]), "r"((a)[2]), "r"((a)[3]),                \
          "r"(b0), "r"(b1))

// SMEM geometry: row = [64B slice1][64B slice2][16B pad], stride 144 (9*16 -> cf)
// CTA tile 64(m) x 128(n), BK=64. A tile 64 rows, B tile 128 rows.
#define ROW_STR 144
#define TILE_A  (64 * ROW_STR)    // 9216
#define TILE_B  (128 * ROW_STR)   // 18432
#define STAGE_SZ (TILE_A + TILE_B)  // 27648
#define SMEM_TOT (2 * STAGE_SZ)     // 55296 -> 2 CTAs/SM

// ---------------------------------------------------------------------------
// 2-slice int8 GEMM (NT: both A and B stored [rows][K] k-major int8 slices):
//   C[m,n] = (P1 + P2/128) * isa[m] * isb[n]  (+ bias[n])
//   P1 = A1*B1 ; P2 = A1*B2 + A2*B1  (dropped A2*B2/16384 ~ 1e-5 rel)
// 256 threads, 8 warps (2m x 4n), warp tile 32x32. BK=64 (2 x k32 steps).
// cp.async 2-stage, one barrier per chunk (R10-proven skeleton).
// ---------------------------------------------------------------------------
template <bool BIAS>
__global__ __launch_bounds__(256, 2)
void i8_gemm(const s8* __restrict__ A1, const s8* __restrict__ A2,
             const s8* __restrict__ B1, const s8* __restrict__ B2,
             const float* __restrict__ isa, const float* __restrict__ isb,
             const float* __restrict__ bias, float* __restrict__ C,
             int M, int N, int K,
             long zA, long zB, long zC, long zSA, long zSB, long zBias)
{
    extern __shared__ char smem[];
    const uint32_t sb = smem_u32(smem);
    const int tid = threadIdx.x;
    const int lane = tid & 31, wid = tid >> 5;
    const int bm = blockIdx.x * 64, bn = blockIdx.y * 128;
    const int wm = (wid & 1) * 32, wn = (wid >> 1) * 32;

    A1 += (long)blockIdx.z * zA;  A2 += (long)blockIdx.z * zA;
    B1 += (long)blockIdx.z * zB;  B2 += (long)blockIdx.z * zB;
    isa += (long)blockIdx.z * zSA;
    isb += (long)blockIdx.z * zSB;
    if (BIAS) bias += (long)blockIdx.z * zBias;
    C += (long)blockIdx.z * zC;

    int acc1[2][4][4], acc2[2][4][4];
#pragma unroll
    for (int i = 0; i < 2; i++)
#pragma unroll
        for (int j = 0; j < 4; j++)
#pragma unroll
            for (int r = 0; r < 4; r++) { acc1[i][j][r] = 0; acc2[i][j][r] = 0; }

    // staging: A 64 rows x 4 chunks (1/thr/slice); B 128 rows (2/thr/slice)
    const int ar = tid >> 2, ac = tid & 3;

    auto issue_stage = [&](int slot, int ch) {
        const uint32_t st = sb + slot * STAGE_SZ;
        const int k0 = ch << 6;
        {
            long off = (long)(bm + ar) * K + k0 + ac * 16;
            uint32_t d = st + ar * ROW_STR + ac * 16;
            CPA16(d, A1 + off);
            CPA16(d + 64, A2 + off);
        }
#pragma unroll
        for (int rep = 0; rep < 2; rep++) {
            int idx = tid + rep * 256;
            int r = idx >> 2, c = idx & 3;
            long off = (long)(bn + r) * K + k0 + c * 16;
            uint32_t d = st + TILE_A + r * ROW_STR + c * 16;
            CPA16(d, B1 + off);
            CPA16(d + 64, B2 + off);
        }
    };

    const int NCH = K >> 6;

    issue_stage(0, 0); CP_COMMIT();

    for (int ch = 0; ch < NCH; ch++) {
        const int buf = ch & 1;
        CP_WAIT0();
        __syncthreads();

        const uint32_t stg = sb + buf * STAGE_SZ;
        const uint32_t a_base = stg;
        const uint32_t b_base = stg + TILE_A;

        bool first = true;
#pragma unroll
        for (int ks = 0; ks < 2; ks++) {
            const int kb = ks * 32;     // byte offset within 64B slice
            // ---- A fragments: 2 i-tiles x 2 slices ----
            uint32_t a1[2][4], a2[2][4];
            {
                const int arr = wm + (lane & 15);
                const int acc_ = kb + (lane >> 4) * 16;
#pragma unroll
                for (int i = 0; i < 2; i++) {
                    uint32_t ad = a_base + (arr + i * 16) * ROW_STR + acc_;
                    LDSM4(a1[i][0], a1[i][1], a1[i][2], a1[i][3], ad);
                    LDSM4(a2[i][0], a2[i][1], a2[i][2], a2[i][3], ad + 64);
                }
            }
            // ---- B fragments: 2 n16-tiles x 2 slices ----
            uint32_t b1[2][4], b2[2][4];
            {
                const int br = wn + (lane & 7) + (lane >> 4) * 8;
                const int bc = kb + ((lane >> 3) & 1) * 16;
#pragma unroll
                for (int jj = 0; jj < 2; jj++) {
                    uint32_t bd = b_base + (br + jj * 16) * ROW_STR + bc;
                    LDSM4(b1[jj][0], b1[jj][1], b1[jj][2], b1[jj][3], bd);
                    LDSM4(b2[jj][0], b2[jj][1], b2[jj][2], b2[jj][3], bd + 64);
                }
            }
            // overlap next-chunk cp.async issue with this k32's MMAs
            if (first && ch + 1 < NCH) {
                issue_stage(buf ^ 1, ch + 1);
                CP_COMMIT();
            }
            first = false;
            // ---- 24 IMMA, integer-exact ----
#pragma unroll
            for (int i = 0; i < 2; i++)
#pragma unroll
                for (int jj = 0; jj < 2; jj++)
#pragma unroll
                    for (int h = 0; h < 2; h++) {
                        int* d1 = acc1[i][jj * 2 + h];
                        int* d2 = acc2[i][jj * 2 + h];
                        MMA_S8(d1, a1[i], b1[jj][2 * h], b1[jj][2 * h + 1]);
                        MMA_S8(d2, a1[i], b2[jj][2 * h], b2[jj][2 * h + 1]);
                        MMA_S8(d2, a2[i], b1[jj][2 * h], b1[jj][2 * h + 1]);
                    }
        }
    }

    // ---- epilogue: combine slices, rescale, bias ----
#pragma unroll
    for (int i = 0; i < 2; i++) {
        const int m0 = bm + wm + i * 16 + (lane >> 2);
        const float ia0 = isa[m0], ia1 = isa[m0 + 8];
#pragma unroll
        for (int j = 0; j < 4; j++) {
            const int n0 = bn + wn + j * 8 + (lane & 3) * 2;
            const float ib0 = isb[n0], ib1 = isb[n0 + 1];
            float f0 = (float)acc1[i][j][0] + (float)acc2[i][j][0] * 0.0078125f;
            float f1 = (float)acc1[i][j][1] + (float)acc2[i][j][1] * 0.0078125f;
            float f2 = (float)acc1[i][j][2] + (float)acc2[i][j][2] * 0.0078125f;
            float f3 = (float)acc1[i][j][3] + (float)acc2[i][j][3] * 0.0078125f;
            float v0 = f0 * ia0 * ib0, v1 = f1 * ia0 * ib1;
            float v2 = f2 * ia1 * ib0, v3 = f3 * ia1 * ib1;
            if (BIAS) {
                float bx = bias[n0], by = bias[n0 + 1];
                v0 += bx; v1 += by; v2 += bx; v3 += by;
            }
            long o = (long)m0 * N + n0;
            *(float2*)(C + o) = make_float2(v0, v1);
            *(float2*)(C + o + (long)8 * N) = make_float2(v2, v3);
        }
    }
}

// ---------------------------------------------------------------------------
// Row conversion: fp32 row of 1024 -> per-row scale + 2 int8 slices
// ---------------------------------------------------------------------------
__device__ __forceinline__ void conv_row_body(const float* __restrict__ rowp,
                                              s8* __restrict__ o1,
                                              s8* __restrict__ o2,
                                              float* __restrict__ invp)
{
    const int tid = threadIdx.x;
    __shared__ float red[256];
    float4 v = ((const float4*)rowp)[tid];
    float m = fmaxf(fmaxf(fabsf(v.x), fabsf(v.y)), fmaxf(fabsf(v.z), fabsf(v.w)));
    red[tid] = m;
    __syncthreads();
#pragma unroll
    for (int o = 128; o > 0; o >>= 1) {
        if (tid < o) red[tid] = fmaxf(red[tid], red[tid + o]);
        __syncthreads();
    }
    float mx = fmaxf(red[0], 1e-30f);
    float s = 126.f / mx;
    if (tid == 0) *invp = mx * (1.f / 126.f);
    float xs[4] = {v.x, v.y, v.z, v.w};
    char q1[4], q2[4];
#pragma unroll
    for (int e = 0; e < 4; e++) {
        float vs = xs[e] * s;
        int a = __float2int_rn(vs);
        q1[e] = (char)a;
        q2[e] = (char)__float2int_rn((vs - (float)a) * 128.f);
    }
    ((char4*)o1)[tid] = *(char4*)q1;
    ((char4*)o2)[tid] = *(char4*)q2;
}

__global__ __launch_bounds__(256)
void conv_rows(const float* __restrict__ in, s8* __restrict__ o1,
               s8* __restrict__ o2, float* __restrict__ inv)
{
    size_t row = blockIdx.x;
    conv_row_body(in + row * DD, o1 + row * DD, o2 + row * DD, inv + row);
}

__global__ __launch_bounds__(256)
void conv3_rows(const float* __restrict__ a, const float* __restrict__ b,
                const float* __restrict__ c, s8* __restrict__ o1,
                s8* __restrict__ o2, float* __restrict__ inv)
{
    const float* in = (blockIdx.y == 0) ? a : (blockIdx.y == 1) ? b : c;
    size_t row = blockIdx.x;
    size_t orow = (size_t)blockIdx.y * MTOT + row;
    conv_row_body(in + row * DD, o1 + orow * DD, o2 + orow * DD, inv + orow);
}

__global__ __launch_bounds__(256)
void conv4_rows(const float* __restrict__ a, const float* __restrict__ b,
                const float* __restrict__ c, const float* __restrict__ d,
                s8* __restrict__ o1, s8* __restrict__ o2, float* __restrict__ inv)
{
    const float* in = (blockIdx.y == 0) ? a : (blockIdx.y == 1) ? b
                    : (blockIdx.y == 2) ? c : d;
    size_t row = blockIdx.x;
    size_t orow = (size_t)blockIdx.y * DD + row;
    conv_row_body(in + row * DD, o1 + orow * DD, o2 + orow * DD, inv + orow);
}

// ---------------------------------------------------------------------------
// V transpose-convert: v fp32 [b][token][d] -> Vt int8 slices [b][d][token],
// per-(b,d) column scale. Block = (32 d-cols, one batch).
// ---------------------------------------------------------------------------
__global__ __launch_bounds__(256)
void conv_vT(const float* __restrict__ vsrc, s8* __restrict__ o1,
             s8* __restrict__ o2, float* __restrict__ inv)
{
    const int b = blockIdx.y;
    const int d0 = blockIdx.x * 32;
    const float* v = vsrc + (size_t)b * SS * DD;
    const int c = threadIdx.x & 31, g = threadIdx.x >> 5;
    __shared__ float red[256];
    __shared__ float scale[32];
    __shared__ __align__(16) char t1[32][272];
    __shared__ __align__(16) char t2[32][272];

    float m = 0.f;
    for (int t = g; t < SS; t += 8)
        m = fmaxf(m, fabsf(v[(size_t)t * DD + d0 + c]));
    red[g * 32 + c] = m;
    __syncthreads();
    if (g == 0) {
        float mm = red[c];
#pragma unroll
        for (int gg = 1; gg < 8; gg++) mm = fmaxf(mm, red[gg * 32 + c]);
        mm = fmaxf(mm, 1e-30f);
        scale[c] = 126.f / mm;
        inv[(size_t)b * DD + d0 + c] = mm * (1.f / 126.f);
    }
    __syncthreads();
    const float s = scale[c];

    for (int ch = 0; ch < SS / 256; ch++) {
        for (int tl = g; tl < 256; tl += 8) {
            float val = v[(size_t)(ch * 256 + tl) * DD + d0 + c] * s;
            int a = __float2int_rn(val);
            t1[c][tl] = (char)a;
            t2[c][tl] = (char)__float2int_rn((val - (float)a) * 128.f);
        }
        __syncthreads();
#pragma unroll
        for (int rep = 0; rep < 2; rep++) {
            int idx = threadIdx.x + rep * 256;
            int cc = idx >> 4, o16 = idx & 15;
            size_t go = ((size_t)b * DD + d0 + cc) * SS + ch * 256 + o16 * 16;
            *(uint4*)(o1 + go) = *(const uint4*)&t1[cc][o16 * 16];
            *(uint4*)(o2 + go) = *(const uint4*)&t2[cc][o16 * 16];
        }
        __syncthreads();
    }
}

// Gather q/k/v biases into one contiguous array
__global__ void copy_bias3(const float* __restrict__ a, const float* __restrict__ b,
                           const float* __restrict__ c, float* __restrict__ d)
{
    int i = blockIdx.x * 256 + threadIdx.x;
    if (i < DD) d[i] = a[i];
    else if (i < 2 * DD) d[i] = b[i - DD];
    else if (i < 3 * DD) d[i] = c[i - 2 * DD];
}

// ---------------------------------------------------------------------------
// Softmax: scale raw scores, softmax per row, emit P int8 slices + scale.
// pmax per row = inv (max exp = 1), so slice scale = 126/inv -> p*126/inv = e*126.
// ---------------------------------------------------------------------------
__global__ __launch_bounds__(256)
void softmax_rows(const float* __restrict__ s, s8* __restrict__ p1,
                  s8* __restrict__ p2, float* __restrict__ sp)
{
    const size_t row = blockIdx.x;
    const float* p = s + row * SS;
    const int tid = threadIdx.x;
    __shared__ float red[256];
    const float SCALE = 0.088388347648318447f;   // 1/sqrt(128)

    float4 v0 = ((const float4*)p)[tid * 2];
    float4 v1 = ((const float4*)p)[tid * 2 + 1];
    float e[8] = {v0.x * SCALE, v0.y * SCALE, v0.z * SCALE, v0.w * SCALE,
                  v1.x * SCALE, v1.y * SCALE, v1.z * SCALE, v1.w * SCALE};

    float mx = -1e30f;
#pragma unroll
    for (int i = 0; i < 8; i++) mx = fmaxf(mx, e[i]);
    red[tid] = mx;
    __syncthreads();
#pragma unroll
    for (int o = 128; o > 0; o >>= 1) {
        if (tid < o) red[tid] = fmaxf(red[tid], red[tid + o]);
        __syncthreads();
    }
    mx = red[0];
    __syncthreads();

    float sum = 0.f;
#pragma unroll
    for (int i = 0; i < 8; i++) { e[i] = __expf(e[i] - mx); sum += e[i]; }
    red[tid] = sum;
    __syncthreads();
#pragma unroll
    for (int o = 128; o > 0; o >>= 1) {
        if (tid < o) red[tid] += red[tid + o];
        __syncthreads();
    }
    const float inv = 1.f / red[0];
    if (tid == 0) sp[row] = inv * (1.f / 126.f);

    char q1[8], q2[8];
#pragma unroll
    for (int i = 0; i < 8; i++) {
        float ps = e[i] * 126.f;            // == p * (126/pmax)
        int a = __float2int_rn(ps);
        q1[i] = (char)a;
        q2[i] = (char)__float2int_rn((ps - (float)a) * 128.f);
    }
    *(uint2*)(p1 + row * SS + tid * 8) = *(uint2*)q1;
    *(uint2*)(p2 + row * SS + tid * 8) = *(uint2*)q2;
}

// ---------------------------------------------------------------------------
extern "C" void kernel_launch(void* const* d_in, const int* in_sizes, int n_in,
                              void* d_out, int out_size)
{
    const float* query = (const float*)d_in[0];
    const float* key   = (const float*)d_in[1];
    const float* value = (const float*)d_in[2];
    const float* Wq = (const float*)d_in[3];
    const float* bq = (const float*)d_in[4];
    const float* Wk = (const float*)d_in[5];
    const float* bk = (const float*)d_in[6];
    const float* Wv = (const float*)d_in[7];
    const float* bv = (const float*)d_in[8];
    const float* Wo = (const float*)d_in[9];
    const float* bo = (const float*)d_in[10];
    float* out = (float*)d_out;

    float *s, *qkvf, *xf, *sin, *sw, *sqk, *sv, *sp, *sx, *bias3;
    s8 *in1, *in2, *w1, *w2, *qk1, *qk2, *vt1, *vt2, *p1, *p2, *x1, *x2;
    cudaGetSymbolAddress((void**)&s, g_s);
    cudaGetSymbolAddress((void**)&in1, g_in1);  cudaGetSymbolAddress((void**)&in2, g_in2);
    cudaGetSymbolAddress((void**)&w1, g_w1);    cudaGetSymbolAddress((void**)&w2, g_w2);
    cudaGetSymbolAddress((void**)&qkvf, g_qkvf);
    cudaGetSymbolAddress((void**)&qk1, g_qk1);  cudaGetSymbolAddress((void**)&qk2, g_qk2);
    cudaGetSymbolAddress((void**)&vt1, g_vt1);  cudaGetSymbolAddress((void**)&vt2, g_vt2);
    cudaGetSymbolAddress((void**)&p1, g_p1);    cudaGetSymbolAddress((void**)&p2, g_p2);
    cudaGetSymbolAddress((void**)&xf, g_xf);
    cudaGetSymbolAddress((void**)&x1, g_x1);    cudaGetSymbolAddress((void**)&x2, g_x2);
    cudaGetSymbolAddress((void**)&sin, g_sin);  cudaGetSymbolAddress((void**)&sw, g_sw);
    cudaGetSymbolAddress((void**)&sqk, g_sqk);  cudaGetSymbolAddress((void**)&sv, g_sv);
    cudaGetSymbolAddress((void**)&sp, g_sp);    cudaGetSymbolAddress((void**)&sx, g_sx);
    cudaGetSymbolAddress((void**)&bias3, g_bias3);

    static bool attr_done = false;
    if (!attr_done) {
        cudaFuncSetAttribute(i8_gemm<true>,
                             cudaFuncAttributeMaxDynamicSharedMemorySize, SMEM_TOT);
        cudaFuncSetAttribute(i8_gemm<false>,
                             cudaFuncAttributeMaxDynamicSharedMemorySize, SMEM_TOT);
        attr_done = true;
    }

    const dim3 blk(256);
    const long WD = (long)DD * DD;
    const long IN = (long)MTOT * DD;

    // ---- conversions (inputs, weights) + bias gather ----
    dim3 g3(MTOT, 3);
    conv3_rows<<<g3, blk>>>(query, key, value, in1, in2, sin);
    dim3 g4(DD, 4);
    conv4_rows<<<g4, blk>>>(Wq, Wk, Wv, Wo, w1, w2, sw);
    copy_bias3<<<12, blk>>>(bq, bk, bv, bias3);

    // ---- merged QKV projections (z = 0..2), fp32 out ----
    dim3 gp(MTOT / 64, DD / 128, 3);
    i8_gemm<true><<<gp, blk, SMEM_TOT>>>(
        in1, in2, w1, w2, sin, sw, bias3, qkvf, MTOT, DD, DD,
        IN, WD, IN, MTOT, DD, DD);

    // ---- convert q,k (rows 0..32767 of qkvf); transpose-convert v ----
    conv_rows<<<2 * MTOT, blk>>>(qkvf, qk1, qk2, sqk);
    dim3 gv(DD / 32, BB);
    conv_vT<<<gv, blk>>>(qkvf + 2 * IN, vt1, vt2, sv);

    // ---- scores: S = q k^T (raw fp32; softmax applies 1/sqrt(128)) ----
    dim3 gs(SS / 64, SS / 128, BB);
    i8_gemm<false><<<gs, blk, SMEM_TOT>>>(
        qk1, qk2, qk1 + IN, qk2 + IN, sqk, sqk + MTOT, nullptr, s,
        SS, SS, DD, (long)SS * DD, (long)SS * DD, (long)SS * SS,
        SS, SS, 0);

    // ---- softmax -> P int8 slices ----
    softmax_rows<<<BB * SS, blk>>>(s, p1, p2, sp);

    // ---- X = P V  (B = Vt [d][token] int8 slices) ----
    dim3 gx(SS / 64, DD / 128, BB);
    i8_gemm<false><<<gx, blk, SMEM_TOT>>>(
        p1, p2, vt1, vt2, sp, sv, nullptr, xf,
        SS, DD, SS, (long)SS * SS, (long)DD * SS, (long)SS * DD,
        SS, DD, 0);

    // ---- convert X; output projection -> fp32 out ----
    conv_rows<<<MTOT, blk>>>(xf, x1, x2, sx);
    dim3 go(MTOT / 64, DD / 128, 1);
    i8_gemm<true><<<go, blk, SMEM_TOT>>>(
        x1, x2, w1 + 3 * WD, w2 + 3 * WD, sx, sw + 3 * DD, bo, out,
        MTOT, DD, DD, 0, 0, 0, 0, 0, 0);
}

// round 15
// speedup vs baseline: 2.6515x; 2.6515x over previous
#include <cuda_runtime.h>
#include <cuda_bf16.h>
#include <cstdint>
#include <math.h>

// Problem constants
#define BB 8
#define SS 2048
#define DD 1024
#define MTOT (BB * SS)   // 16384

typedef __nv_bfloat16 bf16;

// Scratch (device globals; no allocation allowed)
__device__ float g_s[(size_t)BB * SS * SS];            // fp32 scores
__device__ bf16 g_inh[3 * (size_t)MTOT * DD], g_inl[3 * (size_t)MTOT * DD];
__device__ bf16 g_wh[4 * (size_t)DD * DD],  g_wl[4 * (size_t)DD * DD];
__device__ bf16 g_qkvh[3 * (size_t)MTOT * DD], g_qkvl[3 * (size_t)MTOT * DD];
__device__ bf16 g_ph[(size_t)BB * SS * SS], g_pl[(size_t)BB * SS * SS];
__device__ bf16 g_xh[(size_t)MTOT * DD], g_xl[(size_t)MTOT * DD];
__device__ float g_bias3[3 * DD];

// ---------------------------------------------------------------------------
// PTX helpers
// ---------------------------------------------------------------------------
__device__ __forceinline__ uint32_t smem_u32(const void* p) {
    uint32_t a;
    asm("{ .reg .u64 t; cvta.to.shared.u64 t, %1; cvt.u32.u64 %0, t; }"
        : "=r"(a) : "l"(p));
    return a;
}

#define CPA16(dst, src) \
    asm volatile("cp.async.cg.shared.global [%0], [%1], 16;" :: "r"(dst), "l"(src))
#define CP_COMMIT() asm volatile("cp.async.commit_group;" ::: "memory")
#define CP_WAIT0()  asm volatile("cp.async.wait_group 0;" ::: "memory")

#define LDSM4(r0, r1, r2, r3, addr) \
    asm volatile("ldmatrix.sync.aligned.m8n8.x4.shared.b16 {%0,%1,%2,%3}, [%4];" \
                 : "=r"(r0), "=r"(r1), "=r"(r2), "=r"(r3) : "r"(addr))

#define LDSM4T(r0, r1, r2, r3, addr) \
    asm volatile("ldmatrix.sync.aligned.m8n8.x4.trans.shared.b16 {%0,%1,%2,%3}, [%4];" \
                 : "=r"(r0), "=r"(r1), "=r"(r2), "=r"(r3) : "r"(addr))

#define MMA_BF16(d, a, b0, b1)                                              \
    asm volatile(                                                           \
        "mma.sync.aligned.m16n8k16.row.col.f32.bf16.bf16.f32 "              \
        "{%0,%1,%2,%3}, {%4,%5,%6,%7}, {%8,%9}, {%0,%1,%2,%3};"             \
        : "+f"((d)[0]), "+f"((d)[1]), "+f"((d)[2]), "+f"((d)[3])            \
        : "r"((a)[0]), "r"((a)[1]), "r"((a)[2]), "r"((a)[3]),               \
          "r"(b0), "r"(b1))

// fp32 -> bf16 hi/lo split
__device__ __forceinline__ void split1(float v, bf16& h, bf16& l) {
    h = __float2bfloat16_rn(v);
    l = __float2bfloat16_rn(v - __bfloat162float(h));
}

// SMEM geometry (bf16 tiles, BK=32, CTA tile 128x128) — R10 geometry
#define A_STR   80       // 64B data + 16B pad per K-major row
#define BNN_STR 272      // 256B data + 16B pad per NN (n-major) row
#define TILE_A  10240    // 128 * 80
#define TILE_BNN 8704    // 32 * 272
#define STAGE_B 40960
#define SMEM_TOT (2 * STAGE_B)   // 81920 -> 2 CTAs/SM

// ---------------------------------------------------------------------------
// Split-bf16 tensor-core GEMM on pre-split operands, cp.async 2-stage,
// 2 CTAs/SM, ONE barrier per chunk (exact R10 champion loop):
//   C = A @ B' (+bias);  D = Ahi*Bhi + Alo*Bhi + Ahi*Blo
// CTA tile 128x128, BK=32, 256 threads (8 warps 2m x 4n), warp tile 64x32.
// ---------------------------------------------------------------------------
template <bool BT, bool BIAS, bool OUT_SPLIT>
__global__ __launch_bounds__(256, 2)
void tc_gemm(const bf16* __restrict__ Ah, const bf16* __restrict__ Al,
             const bf16* __restrict__ Bh, const bf16* __restrict__ Bl,
             const float* __restrict__ bias,
             float* __restrict__ C, bf16* __restrict__ Ch, bf16* __restrict__ Cl,
             int M, int N, int K,
             long sA, long sB, long sC, long sBias)
{
    extern __shared__ char smem[];
    const uint32_t sb = smem_u32(smem);
    const int tid = threadIdx.x;
    const int lane = tid & 31, wid = tid >> 5;
    const int bm = blockIdx.x * 128, bn = blockIdx.y * 128;
    const int wm = (wid & 1) * 64, wn = (wid >> 1) * 32;

    Ah += (long)blockIdx.z * sA;  Al += (long)blockIdx.z * sA;
    Bh += (long)blockIdx.z * sB;  Bl += (long)blockIdx.z * sB;
    if (BIAS) bias += (long)blockIdx.z * sBias;

    float acc[4][4][4];
#pragma unroll
    for (int i = 0; i < 4; i++)
#pragma unroll
        for (int j = 0; j < 4; j++)
#pragma unroll
            for (int r = 0; r < 4; r++) acc[i][j][r] = 0.f;

    const int arow = tid >> 2, acol = tid & 3;
    const int bkrow = tid >> 4, bkcol = tid & 15;

    auto issue_stage = [&](int slot, int ch) {
        const uint32_t st = sb + slot * STAGE_B;
        const int k0 = ch << 5;
        {
            long off = (long)(bm + arow) * K + k0 + acol * 8;
            long off2 = off + (long)64 * K;
            uint32_t d = st + arow * A_STR + acol * 16;
            uint32_t d2 = d + 64 * A_STR;
            CPA16(d, Ah + off);            CPA16(d + TILE_A, Al + off);
            CPA16(d2, Ah + off2);          CPA16(d2 + TILE_A, Al + off2);
        }
        if (BT) {
            long off = (long)(bn + arow) * K + k0 + acol * 8;
            long off2 = off + (long)64 * K;
            uint32_t d = st + 2 * TILE_A + arow * A_STR + acol * 16;
            uint32_t d2 = d + 64 * A_STR;
            CPA16(d, Bh + off);            CPA16(d + TILE_A, Bl + off);
            CPA16(d2, Bh + off2);          CPA16(d2 + TILE_A, Bl + off2);
        } else {
            long off = (long)(k0 + bkrow) * N + bn + bkcol * 8;
            long off2 = off + (long)16 * N;
            uint32_t d = st + 2 * TILE_A + bkrow * BNN_STR + bkcol * 16;
            uint32_t d2 = d + 16 * BNN_STR;
            CPA16(d, Bh + off);            CPA16(d + TILE_BNN, Bl + off);
            CPA16(d2, Bh + off2);          CPA16(d2 + TILE_BNN, Bl + off2);
        }
    };

    const int NCH = K >> 5;

    issue_stage(0, 0); CP_COMMIT();

    for (int ch = 0; ch < NCH; ch++) {
        const int buf = ch & 1;
        CP_WAIT0();          // only chunk ch outstanding -> chunk ch complete
        __syncthreads();     // data visible to all warps; prev-chunk reads done

        const uint32_t stg = sb + buf * STAGE_B;
        const uint32_t a_hi = stg, a_lo = stg + TILE_A;
        const uint32_t b_hi = stg + 2 * TILE_A;
        const uint32_t b_lo = b_hi + (BT ? TILE_A : TILE_BNN);

        bool first = true;
#pragma unroll
        for (int ks = 0; ks < 2; ks++) {
            const int k16 = ks * 16;
            uint32_t ah[4][4], al[4][4];
            {
                const int ar = wm + (lane & 15);
                const int ac = (k16 + (lane >> 4) * 8) * 2;
#pragma unroll
                for (int i = 0; i < 4; i++) {
                    uint32_t ad = a_hi + (ar + i * 16) * A_STR + ac;
                    LDSM4(ah[i][0], ah[i][1], ah[i][2], ah[i][3], ad);
                    uint32_t ad2 = a_lo + (ar + i * 16) * A_STR + ac;
                    LDSM4(al[i][0], al[i][1], al[i][2], al[i][3], ad2);
                }
            }
            uint32_t bb[2][4];
            // ---- B_hi: terms Ahi*Bhi and Alo*Bhi ----
            if (BT) {
                const int br = wn + (lane & 7) + (lane >> 4) * 8;
                const int bc = (k16 + ((lane >> 3) & 1) * 8) * 2;
#pragma unroll
                for (int j = 0; j < 2; j++) {
                    uint32_t bd = b_hi + (br + j * 16) * A_STR + bc;
                    LDSM4(bb[j][0], bb[j][1], bb[j][2], bb[j][3], bd);
                }
            } else {
                const int bk = k16 + (lane & 7) + ((lane >> 3) & 1) * 8;
                const int bcol = (wn + (lane >> 4) * 8) * 2;
#pragma unroll
                for (int j = 0; j < 2; j++) {
                    uint32_t bd = b_hi + bk * BNN_STR + bcol + j * 32;
                    LDSM4T(bb[j][0], bb[j][1], bb[j][2], bb[j][3], bd);
                }
            }
            // overlap next-chunk cp.async issue with this k16's MMAs
            if (first && ch + 1 < NCH) {
                issue_stage(buf ^ 1, ch + 1);
                CP_COMMIT();
            }
            first = false;
#pragma unroll
            for (int i = 0; i < 4; i++)
#pragma unroll
                for (int j = 0; j < 2; j++)
#pragma unroll
                    for (int h = 0; h < 2; h++) {
                        MMA_BF16(acc[i][j * 2 + h], ah[i], bb[j][2 * h], bb[j][2 * h + 1]);
                        MMA_BF16(acc[i][j * 2 + h], al[i], bb[j][2 * h], bb[j][2 * h + 1]);
                    }
            // ---- B_lo: term Ahi*Blo (reuse bb regs) ----
            if (BT) {
                const int br = wn + (lane & 7) + (lane >> 4) * 8;
                const int bc = (k16 + ((lane >> 3) & 1) * 8) * 2;
#pragma unroll
                for (int j = 0; j < 2; j++) {
                    uint32_t bd = b_lo + (br + j * 16) * A_STR + bc;
                    LDSM4(bb[j][0], bb[j][1], bb[j][2], bb[j][3], bd);
                }
            } else {
                const int bk = k16 + (lane & 7) + ((lane >> 3) & 1) * 8;
                const int bcol = (wn + (lane >> 4) * 8) * 2;
#pragma unroll
                for (int j = 0; j < 2; j++) {
                    uint32_t bd = b_lo + bk * BNN_STR + bcol + j * 32;
                    LDSM4T(bb[j][0], bb[j][1], bb[j][2], bb[j][3], bd);
                }
            }
#pragma unroll
            for (int i = 0; i < 4; i++)
#pragma unroll
                for (int j = 0; j < 2; j++)
#pragma unroll
                    for (int h = 0; h < 2; h++)
                        MMA_BF16(acc[i][j * 2 + h], ah[i], bb[j][2 * h], bb[j][2 * h + 1]);
        }
        // no trailing barrier: next iteration's post-wait barrier orders
        // this chunk's reads before the following issue into this slot.
    }

    // ---- epilogue ----
#pragma unroll
    for (int i = 0; i < 4; i++) {
        const int m0 = bm + wm + i * 16 + (lane >> 2);
#pragma unroll
        for (int jj = 0; jj < 4; jj++) {
            const int n0 = bn + wn + jj * 8 + (lane & 3) * 2;
            float v0 = acc[i][jj][0], v1 = acc[i][jj][1];
            float v2 = acc[i][jj][2], v3 = acc[i][jj][3];
            if (BIAS) {
                float bx = bias[n0], by = bias[n0 + 1];
                v0 += bx; v1 += by; v2 += bx; v3 += by;
            }
            if (OUT_SPLIT) {
                bf16 h0, l0, h1, l1;
                split1(v0, h0, l0); split1(v1, h1, l1);
                __nv_bfloat162 hh = {h0, h1}, ll = {l0, l1};
                long o = (long)blockIdx.z * sC + (long)m0 * N + n0;
                *(uint32_t*)(Ch + o) = *(uint32_t*)&hh;
                *(uint32_t*)(Cl + o) = *(uint32_t*)&ll;
                split1(v2, h0, l0); split1(v3, h1, l1);
                __nv_bfloat162 hh2 = {h0, h1}, ll2 = {l0, l1};
                long o2 = o + (long)8 * N;
                *(uint32_t*)(Ch + o2) = *(uint32_t*)&hh2;
                *(uint32_t*)(Cl + o2) = *(uint32_t*)&ll2;
            } else {
                long o = (long)blockIdx.z * sC + (long)m0 * N + n0;
                *(float2*)(C + o) = make_float2(v0, v1);
                *(float2*)(C + o + (long)8 * N) = make_float2(v2, v3);
            }
        }
    }
}

// ---------------------------------------------------------------------------
// Merged elementwise splits: 3 inputs (blockIdx.y selects tensor)
// ---------------------------------------------------------------------------
__global__ __launch_bounds__(256)
void split_in3(const float* __restrict__ a, const float* __restrict__ b,
               const float* __restrict__ c, bf16* __restrict__ hi,
               bf16* __restrict__ lo)
{
    const float* in = (blockIdx.y == 0) ? a : (blockIdx.y == 1) ? b : c;
    size_t base = (size_t)blockIdx.y * ((size_t)MTOT * DD / 4);
    size_t i = base + blockIdx.x * 256 + threadIdx.x;
    float4 v = ((const float4*)in)[blockIdx.x * 256 + threadIdx.x];
    bf16 h0, l0, h1, l1, h2, l2, h3, l3;
    split1(v.x, h0, l0); split1(v.y, h1, l1);
    split1(v.z, h2, l2); split1(v.w, h3, l3);
    __nv_bfloat162 ha = {h0, h1}, hb = {h2, h3};
    __nv_bfloat162 la = {l0, l1}, lb = {l2, l3};
    ((uint2*)hi)[i] = make_uint2(*(uint32_t*)&ha, *(uint32_t*)&hb);
    ((uint2*)lo)[i] = make_uint2(*(uint32_t*)&la, *(uint32_t*)&lb);
}

// Merged weight splits: 4 weights (blockIdx.y selects tensor)
__global__ __launch_bounds__(256)
void split_w4(const float* __restrict__ a, const float* __restrict__ b,
              const float* __restrict__ c, const float* __restrict__ d,
              bf16* __restrict__ hi, bf16* __restrict__ lo)
{
    const float* in = (blockIdx.y == 0) ? a : (blockIdx.y == 1) ? b
                    : (blockIdx.y == 2) ? c : d;
    size_t base = (size_t)blockIdx.y * ((size_t)DD * DD / 4);
    size_t i = base + blockIdx.x * 256 + threadIdx.x;
    float4 v = ((const float4*)in)[blockIdx.x * 256 + threadIdx.x];
    bf16 h0, l0, h1, l1, h2, l2, h3, l3;
    split1(v.x, h0, l0); split1(v.y, h1, l1);
    split1(v.z, h2, l2); split1(v.w, h3, l3);
    __nv_bfloat162 ha = {h0, h1}, hb = {h2, h3};
    __nv_bfloat162 la = {l0, l1}, lb = {l2, l3};
    ((uint2*)hi)[i] = make_uint2(*(uint32_t*)&ha, *(uint32_t*)&hb);
    ((uint2*)lo)[i] = make_uint2(*(uint32_t*)&la, *(uint32_t*)&lb);
}

// Gather q/k/v biases into one contiguous array
__global__ void copy_bias3(const float* __restrict__ a, const float* __restrict__ b,
                           const float* __restrict__ c, float* __restrict__ d)
{
    int i = blockIdx.x * 256 + threadIdx.x;
    if (i < DD) d[i] = a[i];
    else if (i < 2 * DD) d[i] = b[i - DD];
    else if (i < 3 * DD) d[i] = c[i - 2 * DD];
}

// ---------------------------------------------------------------------------
// Softmax: scale raw scores, softmax per row, write P as bf16 hi/lo.
// ---------------------------------------------------------------------------
__global__ __launch_bounds__(256)
void softmax_rows(const float* __restrict__ s, bf16* __restrict__ ph,
                  bf16* __restrict__ pl)
{
    const long row = blockIdx.x;
    const float* p = s + row * SS;
    const int tid = threadIdx.x;
    __shared__ float red[256];
    const float SCALE = 0.088388347648318447f;   // 1/sqrt(128)

    float4 v0 = ((const float4*)p)[tid * 2];
    float4 v1 = ((const float4*)p)[tid * 2 + 1];
    float e[8] = {v0.x * SCALE, v0.y * SCALE, v0.z * SCALE, v0.w * SCALE,
                  v1.x * SCALE, v1.y * SCALE, v1.z * SCALE, v1.w * SCALE};

    float mx = -1e30f;
#pragma unroll
    for (int i = 0; i < 8; i++) mx = fmaxf(mx, e[i]);
    red[tid] = mx;
    __syncthreads();
#pragma unroll
    for (int o = 128; o > 0; o >>= 1) {
        if (tid < o) red[tid] = fmaxf(red[tid], red[tid + o]);
        __syncthreads();
    }
    mx = red[0];
    __syncthreads();

    float sum = 0.f;
#pragma unroll
    for (int i = 0; i < 8; i++) { e[i] = __expf(e[i] - mx); sum += e[i]; }
    red[tid] = sum;
    __syncthreads();
#pragma unroll
    for (int o = 128; o > 0; o >>= 1) {
        if (tid < o) red[tid] += red[tid + o];
        __syncthreads();
    }
    const float inv = 1.f / red[0];

    bf16 h[8], l[8];
#pragma unroll
    for (int i = 0; i < 8; i++) split1(e[i] * inv, h[i], l[i]);
    ((uint4*)(ph + row * SS))[tid] = *(uint4*)h;
    ((uint4*)(pl + row * SS))[tid] = *(uint4*)l;
}

// ---------------------------------------------------------------------------
extern "C" void kernel_launch(void* const* d_in, const int* in_sizes, int n_in,
                              void* d_out, int out_size)
{
    const float* query = (const float*)d_in[0];
    const float* key   = (const float*)d_in[1];
    const float* value = (const float*)d_in[2];
    const float* Wq = (const float*)d_in[3];
    const float* bq = (const float*)d_in[4];
    const float* Wk = (const float*)d_in[5];
    const float* bk = (const float*)d_in[6];
    const float* Wv = (const float*)d_in[7];
    const float* bv = (const float*)d_in[8];
    const float* Wo = (const float*)d_in[9];
    const float* bo = (const float*)d_in[10];
    float* out = (float*)d_out;

    float *s, *bias3;
    bf16 *inh, *inl, *wh, *wl, *qkvh, *qkvl, *ph, *pl, *xh, *xl;
    cudaGetSymbolAddress((void**)&s, g_s);
    cudaGetSymbolAddress((void**)&inh, g_inh);   cudaGetSymbolAddress((void**)&inl, g_inl);
    cudaGetSymbolAddress((void**)&wh, g_wh);     cudaGetSymbolAddress((void**)&wl, g_wl);
    cudaGetSymbolAddress((void**)&qkvh, g_qkvh); cudaGetSymbolAddress((void**)&qkvl, g_qkvl);
    cudaGetSymbolAddress((void**)&ph, g_ph);     cudaGetSymbolAddress((void**)&pl, g_pl);
    cudaGetSymbolAddress((void**)&xh, g_xh);     cudaGetSymbolAddress((void**)&xl, g_xl);
    cudaGetSymbolAddress((void**)&bias3, g_bias3);

    static bool attr_done = false;
    if (!attr_done) {
        cudaFuncSetAttribute(tc_gemm<true, true, true>,
                             cudaFuncAttributeMaxDynamicSharedMemorySize, SMEM_TOT);
        cudaFuncSetAttribute(tc_gemm<true, false, false>,
                             cudaFuncAttributeMaxDynamicSharedMemorySize, SMEM_TOT);
        cudaFuncSetAttribute(tc_gemm<false, false, true>,
                             cudaFuncAttributeMaxDynamicSharedMemorySize, SMEM_TOT);
        cudaFuncSetAttribute(tc_gemm<true, true, false>,
                             cudaFuncAttributeMaxDynamicSharedMemorySize, SMEM_TOT);
        attr_done = true;
    }

    const dim3 blk(256);
    const size_t WD = (size_t)DD * DD;
    const size_t IN = (size_t)MTOT * DD;

    // ---- splits + bias gather (merged launches) ----
    dim3 gin(MTOT * DD / 1024, 3);
    split_in3<<<gin, blk>>>(query, key, value, inh, inl);
    dim3 gw(DD * DD / 1024, 4);
    split_w4<<<gw, blk>>>(Wq, Wk, Wv, Wo, wh, wl);
    copy_bias3<<<12, blk>>>(bq, bk, bv, bias3);

    // ---- merged QKV projections: one launch, z in [0,3) ----
    dim3 gp(MTOT / 128, DD / 128, 3);
    tc_gemm<true, true, true><<<gp, blk, SMEM_TOT>>>(
        inh, inl, wh, wl, bias3, nullptr, qkvh, qkvl, MTOT, DD, DD,
        (long)IN, (long)WD, (long)IN, (long)DD);

    // ---- scores: S = Q K^T (raw; scale folded into softmax) ----
    dim3 gs(SS / 128, SS / 128, BB);
    tc_gemm<true, false, false><<<gs, blk, SMEM_TOT>>>(
        qkvh, qkvl, qkvh + IN, qkvl + IN, nullptr, s, nullptr, nullptr,
        SS, SS, DD, (long)SS * DD, (long)SS * DD, (long)SS * SS, 0);

    // ---- softmax -> P (bf16 hi/lo) ----
    softmax_rows<<<BB * SS, blk>>>(s, ph, pl);

    // ---- X = P V (NN, split output) ----
    dim3 gx(SS / 128, DD / 128, BB);
    tc_gemm<false, false, true><<<gx, blk, SMEM_TOT>>>(
        ph, pl, qkvh + 2 * IN, qkvl + 2 * IN, nullptr, nullptr, xh, xl,
        SS, DD, SS, (long)SS * SS, (long)SS * DD, (long)SS * DD, 0);

    // ---- output projection -> fp32 out ----
    dim3 go(MTOT / 128, DD / 128, 1);
    tc_gemm<true, true, false><<<go, blk, SMEM_TOT>>>(
        xh, xl, wh + 3 * WD, wl + 3 * WD, bo, out, nullptr, nullptr,
        MTOT, DD, DD, 0, 0, 0, 0);
}